// round 14
// baseline (speedup 1.0000x reference)
#include <cuda_runtime.h>
#include <cuda_fp16.h>

// EdgeMLP via mma.sync tensor cores.
// Per warp: 32 edges. Each thread gathers one edge's endpoints (fp16 node
// table, 16B -> 1 LDG.128 each), builds A-row [sum(6),dif(6),feH,feTH,1,0]
// (K=16) in smem, ldmatrix.x4 -> 2 m16-tiles.
// Stage 1: C(16x24) = A @ B1, 3x mma.m16n8k16 per m-tile, f32 accum.
//   B1 cols 0-9 = fwd hidden (Ws;Wd;w1e;0;b1), 10-19 = rev (Ws;-Wd;0;w1e;b1).
// relu + pack -> A' fragments (identity of layouts: D(m16n8) == A(m16k8)).
// Stage 2: logits = relu(H)(16x24) @ W2p(24x8, col0 = 0.5*w2diff), 3x
//   mma.m16n8k8 per m-tile, f32 accum. col0 rows = per-edge logit.
// out = sigmoid(logit + b2diff).  (softmax(2)[:,1] == sigmoid(logit diff))

#define N_NODES 100000
#define HID 10

struct ParamBlob {
    unsigned int b1f[3][32][2];   // stage-1 B fragments, per n-tile per lane
    unsigned int b2f[3][32];      // stage-2 B fragments, per k-chunk per lane
    float b2d;
};

__device__   ParamBlob g_blob;
__constant__ ParamBlob c_blob;

__device__ uint4 g_xtab[N_NODES];

__device__ __forceinline__ __half2 u2h(unsigned int u)
{
    return *reinterpret_cast<__half2*>(&u);
}
__device__ __forceinline__ unsigned int h2u(__half2 h)
{
    return *reinterpret_cast<unsigned int*>(&h);
}

// B1(k, c) in fp32. c: 0-9 fwd j=c, 10-19 rev j=c-10, 20-23 zero.
__device__ float b1_val(const float* W1, const float* b1, int k, int c)
{
    if (c >= 20) return 0.0f;
    bool fwd = c < 10;
    int j = fwd ? c : c - 10;
    if (k < 6)  return 0.5f * (W1[k * HID + j] + W1[(6 + k) * HID + j]);       // Ws
    if (k < 12) {
        int i = k - 6;
        float wd = 0.5f * (W1[i * HID + j] - W1[(6 + i) * HID + j]);           // Wd
        return fwd ? wd : -wd;
    }
    if (k == 12) return fwd ? W1[12 * HID + j] : 0.0f;                          // fe row
    if (k == 13) return fwd ? 0.0f : W1[12 * HID + j];                          // feT row
    if (k == 14) return b1[j];                                                  // bias row
    return 0.0f;                                                                // k == 15
}

__device__ float w2_val(const float* W2, int h)
{
    if (h < 10) return 0.5f * (W2[h * 2 + 1] - W2[h * 2]);
    if (h < 20) { int j = h - 10; return 0.5f * (W2[j * 2 + 1] - W2[j * 2]); }
    return 0.0f;
}

__global__ void precompute_kernel(const float* __restrict__ x,
                                  const float* __restrict__ W1,
                                  const float* __restrict__ b1,
                                  const float* __restrict__ W2,
                                  const float* __restrict__ b2,
                                  int N)
{
    int tid = threadIdx.x;
    int n = blockIdx.x * blockDim.x + tid;

    if (blockIdx.x == 0) {
        if (tid < 96) {                       // stage-1 B fragments
            int nt = tid >> 5, lane = tid & 31;
            int t = lane & 3, g = lane >> 2;
            int c = nt * 8 + g;
            __half lo0 = __float2half(b1_val(W1, b1, 2 * t,     c));
            __half hi0 = __float2half(b1_val(W1, b1, 2 * t + 1, c));
            __half lo1 = __float2half(b1_val(W1, b1, 2 * t + 8, c));
            __half hi1 = __float2half(b1_val(W1, b1, 2 * t + 9, c));
            g_blob.b1f[nt][lane][0] = h2u(__halves2half2(lo0, hi0));
            g_blob.b1f[nt][lane][1] = h2u(__halves2half2(lo1, hi1));
        } else if (tid < 192) {               // stage-2 B fragments (col0 only)
            int kc = (tid - 96) >> 5, lane = (tid - 96) & 31;
            int t = lane & 3, g = lane >> 2;
            unsigned int u = 0u;
            if (g == 0) {
                __half lo = __float2half(w2_val(W2, 8 * kc + 2 * t));
                __half hi = __float2half(w2_val(W2, 8 * kc + 2 * t + 1));
                u = h2u(__halves2half2(lo, hi));
            }
            g_blob.b2f[kc][lane] = u;
        } else if (tid == 192) {
            g_blob.b2d = b2[1] - b2[0];
        }
    }

    if (n >= N) return;

    float x0 = x[n * 6 + 0], x1 = x[n * 6 + 1], x2 = x[n * 6 + 2];
    float x3 = x[n * 6 + 3], x4 = x[n * 6 + 4], x5 = x[n * 6 + 5];
    g_xtab[n] = make_uint4(h2u(__floats2half2_rn(x0, x1)),
                           h2u(__floats2half2_rn(x2, x3)),
                           h2u(__floats2half2_rn(x4, x5)),
                           0u);
}

__global__ __launch_bounds__(256)
void edge_kernel(const int* __restrict__ ei,        // [2, E] int32
                 const float* __restrict__ ea,
                 const float* __restrict__ eaT,
                 float* __restrict__ out,
                 int E, int N)
{
    // per-warp A staging: 32 rows x 48 B (conflict-free for STS.128 + LDSM)
    __shared__ __align__(16) unsigned int smemA[8 * 384];

    int warp = threadIdx.x >> 5;
    int lane = threadIdx.x & 31;
    int ebase = blockIdx.x * 256 + warp * 32;
    int e = ebase + lane;

    // ---- B fragments from constant (once per thread) ----
    unsigned int bf1[3][2], bf2[3];
    #pragma unroll
    for (int nt = 0; nt < 3; ++nt) {
        bf1[nt][0] = c_blob.b1f[nt][lane][0];
        bf1[nt][1] = c_blob.b1f[nt][lane][1];
        bf2[nt]    = c_blob.b2f[nt][lane];
    }
    float b2d = c_blob.b2d;

    // ---- gather + build A row ----
    int Nm1 = N - 1;
    int s = 0, t = 0;
    float fe = 0.0f, feT = 0.0f;
    bool valid = e < E;
    if (valid) {
        s   = ei[e];
        t   = ei[(size_t)E + e];
        fe  = ea[e];
        feT = eaT[e];
    }
    s = min(max(s, 0), Nm1);
    t = min(max(t, 0), Nm1);

    uint4 xs = __ldg(&g_xtab[s]);
    uint4 xt = __ldg(&g_xtab[t]);

    __half2 sum0 = __hadd2(u2h(xs.x), u2h(xt.x));
    __half2 sum1 = __hadd2(u2h(xs.y), u2h(xt.y));
    __half2 sum2 = __hadd2(u2h(xs.z), u2h(xt.z));
    __half2 dif0 = __hsub2(u2h(xs.x), u2h(xt.x));
    __half2 dif1 = __hsub2(u2h(xs.y), u2h(xt.y));
    __half2 dif2 = __hsub2(u2h(xs.z), u2h(xt.z));

    unsigned int fef;   // lo = feH (k12), hi = feTH (k13)
    asm("cvt.rn.f16x2.f32 %0, %1, %2;" : "=r"(fef) : "f"(feT), "f"(fe));

    unsigned int* rowp = smemA + warp * 384 + lane * 12;   // 48 B per row
    uint4* row4 = reinterpret_cast<uint4*>(rowp);
    row4[0] = make_uint4(h2u(sum0), h2u(sum1), h2u(sum2), h2u(dif0));
    row4[1] = make_uint4(h2u(dif1), h2u(dif2), fef, 0x00003C00u);  // (1,0) tail

    __syncwarp();

    unsigned int smem_u32;
    asm("{ .reg .u64 tmp; cvta.to.shared.u64 tmp, %1; cvt.u32.u64 %0, tmp; }"
        : "=r"(smem_u32) : "l"(smemA));
    unsigned int wbase = smem_u32 + warp * 1536;

    #pragma unroll
    for (int mt = 0; mt < 2; ++mt) {
        // ---- ldmatrix A (16x16) ----
        unsigned int addr = wbase + (mt * 16 + (lane & 15)) * 48 + (lane >> 4) * 16;
        unsigned int a0, a1, a2, a3;
        asm volatile("ldmatrix.sync.aligned.m8n8.x4.shared.b16 {%0,%1,%2,%3}, [%4];"
                     : "=r"(a0), "=r"(a1), "=r"(a2), "=r"(a3) : "r"(addr) : "memory");

        // ---- stage 1: hidden (f32 accum) ----
        float c[3][4];
        #pragma unroll
        for (int nt = 0; nt < 3; ++nt) {
            c[nt][0] = 0.f; c[nt][1] = 0.f; c[nt][2] = 0.f; c[nt][3] = 0.f;
            asm volatile(
                "mma.sync.aligned.m16n8k16.row.col.f32.f16.f16.f32 "
                "{%0,%1,%2,%3}, {%4,%5,%6,%7}, {%8,%9}, {%0,%1,%2,%3};"
                : "+f"(c[nt][0]), "+f"(c[nt][1]), "+f"(c[nt][2]), "+f"(c[nt][3])
                : "r"(a0), "r"(a1), "r"(a2), "r"(a3),
                  "r"(bf1[nt][0]), "r"(bf1[nt][1]));
        }

        // ---- relu + pack to f16 A' fragments ----
        unsigned int h[3][2];
        #pragma unroll
        for (int nt = 0; nt < 3; ++nt) {
            float r0 = fmaxf(c[nt][0], 0.f), r1 = fmaxf(c[nt][1], 0.f);
            float r2 = fmaxf(c[nt][2], 0.f), r3 = fmaxf(c[nt][3], 0.f);
            asm("cvt.rn.f16x2.f32 %0, %1, %2;" : "=r"(h[nt][0]) : "f"(r1), "f"(r0));
            asm("cvt.rn.f16x2.f32 %0, %1, %2;" : "=r"(h[nt][1]) : "f"(r3), "f"(r2));
        }

        // ---- stage 2: logits (f32 accum, col0) ----
        float d0 = 0.f, d1 = 0.f, d2 = 0.f, d3 = 0.f;
        #pragma unroll
        for (int kc = 0; kc < 3; ++kc) {
            asm volatile(
                "mma.sync.aligned.m16n8k8.row.col.f32.f16.f16.f32 "
                "{%0,%1,%2,%3}, {%4,%5}, {%6}, {%0,%1,%2,%3};"
                : "+f"(d0), "+f"(d1), "+f"(d2), "+f"(d3)
                : "r"(h[kc][0]), "r"(h[kc][1]), "r"(bf2[kc]));
        }

        // ---- epilogue: col0 lives at lanes with t==0 ----
        if ((lane & 3) == 0) {
            int g = lane >> 2;
            int ea0 = ebase + mt * 16 + g;
            int ea1 = ea0 + 8;
            if (ea0 < E) {
                float da = d0 + b2d;
                out[ea0] = 1.0f / (1.0f + __expf(-da));
            }
            if (ea1 < E) {
                float db = d2 + b2d;
                out[ea1] = 1.0f / (1.0f + __expf(-db));
            }
        }
    }
}

extern "C" void kernel_launch(void* const* d_in, const int* in_sizes, int n_in,
                              void* d_out, int out_size)
{
    const float* x   = (const float*)d_in[0];
    const int*   ei  = (const int*)d_in[1];
    const float* ea  = (const float*)d_in[2];
    const float* eaT = (const float*)d_in[3];
    const float* W1  = (const float*)d_in[4];
    const float* b1  = (const float*)d_in[5];
    const float* W2  = (const float*)d_in[6];
    const float* b2  = (const float*)d_in[7];
    float*       out = (float*)d_out;

    int N = in_sizes[0] / 6;
    if (N > N_NODES) N = N_NODES;
    int E = in_sizes[2];

    precompute_kernel<<<(N + 255) / 256, 256>>>(x, W1, b1, W2, b2, N);

    void* src = nullptr;
    cudaGetSymbolAddress(&src, g_blob);
    cudaMemcpyToSymbolAsync(c_blob, src, sizeof(ParamBlob), 0,
                            cudaMemcpyDeviceToDevice, 0);

    int blocks = (E + 255) / 256;
    edge_kernel<<<blocks, 256>>>(ei, ea, eaT, out, E, N);
}

// round 15
// speedup vs baseline: 4.4568x; 4.4568x over previous
#include <cuda_runtime.h>
#include <cuda_fp16.h>

// EdgeMLP, gather-minimized, grid-stride depth-8, jp-outer interleaved:
//   node table: x in fp16, 16B record -> ONE LDG.128 per endpoint gather.
//   sum = xs+xt, dif = xs-xt; S = sum@Ws + b1, D = dif@Wd
//   h_f = relu(S + fe*w1e + D),  h_r = relu(S + feT*w1e - D)
//   out = sigmoid((h_f+h_r) . (0.5*w2diff) + b2diff)
// The 4 edges of a quad are advanced TOGETHER through each j-pair so 8
// independent FMA chains are always in flight (hides 4-cyc RAW latency).

#define N_NODES 100000
#define HID 10

struct ParamBlob {
    uint4 pp[5][4];     // per j-pair: Ws[6], Wd[6], w1e, b1, w2d, pad
    float b2d;
    float pad[3];
};

__device__   ParamBlob g_blob;
__constant__ ParamBlob c_blob;

__device__ uint4 g_xtab[N_NODES];

__device__ __forceinline__ __half2 u2h(unsigned int u)
{
    return *reinterpret_cast<__half2*>(&u);
}
__device__ __forceinline__ unsigned int h2u(__half2 h)
{
    return *reinterpret_cast<unsigned int*>(&h);
}

__global__ void precompute_kernel(const float* __restrict__ x,
                                  const float* __restrict__ W1,
                                  const float* __restrict__ b1,
                                  const float* __restrict__ W2,
                                  const float* __restrict__ b2,
                                  int N)
{
    int n = blockIdx.x * blockDim.x + threadIdx.x;

    // parallel param prep: threads 0..4 one j-pair each, thread 5 b2d
    if (blockIdx.x == 0 && threadIdx.x < 5) {
        int jp = threadIdx.x;
        int j0 = 2 * jp, j1 = 2 * jp + 1;
        unsigned int slot[16];
        #pragma unroll
        for (int i = 0; i < 6; ++i) {
            float a0 = W1[i * HID + j0],       a1 = W1[i * HID + j1];
            float c0 = W1[(6 + i) * HID + j0], c1 = W1[(6 + i) * HID + j1];
            slot[i]     = h2u(__floats2half2_rn(0.5f * (a0 + c0), 0.5f * (a1 + c1)));
            slot[6 + i] = h2u(__floats2half2_rn(0.5f * (a0 - c0), 0.5f * (a1 - c1)));
        }
        slot[12] = h2u(__floats2half2_rn(W1[12 * HID + j0], W1[12 * HID + j1]));
        slot[13] = h2u(__floats2half2_rn(b1[j0], b1[j1]));
        slot[14] = h2u(__floats2half2_rn(0.5f * (W2[j0 * 2 + 1] - W2[j0 * 2]),
                                         0.5f * (W2[j1 * 2 + 1] - W2[j1 * 2])));
        slot[15] = 0u;
        g_blob.pp[jp][0] = make_uint4(slot[0],  slot[1],  slot[2],  slot[3]);
        g_blob.pp[jp][1] = make_uint4(slot[4],  slot[5],  slot[6],  slot[7]);
        g_blob.pp[jp][2] = make_uint4(slot[8],  slot[9],  slot[10], slot[11]);
        g_blob.pp[jp][3] = make_uint4(slot[12], slot[13], slot[14], slot[15]);
    }
    if (blockIdx.x == 0 && threadIdx.x == 5) {
        g_blob.b2d = b2[1] - b2[0];
    }

    if (n >= N) return;

    float x0 = x[n * 6 + 0], x1 = x[n * 6 + 1], x2 = x[n * 6 + 2];
    float x3 = x[n * 6 + 3], x4 = x[n * 6 + 4], x5 = x[n * 6 + 5];
    g_xtab[n] = make_uint4(h2u(__floats2half2_rn(x0, x1)),
                           h2u(__floats2half2_rn(x2, x3)),
                           h2u(__floats2half2_rn(x4, x5)),
                           0u);
}

__global__ __launch_bounds__(256, 3)
void edge_kernel(const int* __restrict__ ei,        // [2, E] int32
                 const float* __restrict__ ea,
                 const float* __restrict__ eaT,
                 float* __restrict__ out,
                 int E, int N)
{
    int Nm1 = N - 1;
    int stride = gridDim.x * blockDim.x;
    int tid = blockIdx.x * blockDim.x + threadIdx.x;

    const __half2 zero = __float2half2_rn(0.0f);

    if ((E & 3) == 0) {
        int nq = E >> 2;
        for (int q = tid; q < nq; q += stride) {
            int e0 = q << 2;
            int4   ss = *reinterpret_cast<const int4*>(ei + e0);
            int4   tt = *reinterpret_cast<const int4*>(ei + (size_t)E + e0);
            float4 fe = *reinterpret_cast<const float4*>(ea + e0);
            float4 fT = *reinterpret_cast<const float4*>(eaT + e0);

            int sv[4] = { min(max(ss.x, 0), Nm1), min(max(ss.y, 0), Nm1),
                          min(max(ss.z, 0), Nm1), min(max(ss.w, 0), Nm1) };
            int tv[4] = { min(max(tt.x, 0), Nm1), min(max(tt.y, 0), Nm1),
                          min(max(tt.z, 0), Nm1), min(max(tt.w, 0), Nm1) };

            // 8 front-batched gathers
            uint4 X[4], T[4];
            #pragma unroll
            for (int k = 0; k < 4; ++k) {
                X[k] = __ldg(&g_xtab[sv[k]]);
                T[k] = __ldg(&g_xtab[tv[k]]);
            }

            // broadcast-pair features for all 4 edges
            __half2 bs[4][6], bd[4][6], fe2[4], fT2[4];
            float fev[4] = { fe.x, fe.y, fe.z, fe.w };
            float fTv[4] = { fT.x, fT.y, fT.z, fT.w };
            #pragma unroll
            for (int k = 0; k < 4; ++k) {
                __half2 s0 = __hadd2(u2h(X[k].x), u2h(T[k].x));
                __half2 s1 = __hadd2(u2h(X[k].y), u2h(T[k].y));
                __half2 s2 = __hadd2(u2h(X[k].z), u2h(T[k].z));
                __half2 d0 = __hsub2(u2h(X[k].x), u2h(T[k].x));
                __half2 d1 = __hsub2(u2h(X[k].y), u2h(T[k].y));
                __half2 d2 = __hsub2(u2h(X[k].z), u2h(T[k].z));
                bs[k][0] = __low2half2(s0);  bs[k][1] = __high2half2(s0);
                bs[k][2] = __low2half2(s1);  bs[k][3] = __high2half2(s1);
                bs[k][4] = __low2half2(s2);  bs[k][5] = __high2half2(s2);
                bd[k][0] = __low2half2(d0);  bd[k][1] = __high2half2(d0);
                bd[k][2] = __low2half2(d1);  bd[k][3] = __high2half2(d1);
                bd[k][4] = __low2half2(d2);  bd[k][5] = __high2half2(d2);
                fe2[k] = __float2half2_rn(fev[k]);
                fT2[k] = __float2half2_rn(fTv[k]);
            }

            __half2 acc[4] = { zero, zero, zero, zero };

            // jp-outer: 4 edges advance together -> 8 independent FMA chains
            #pragma unroll
            for (int jp = 0; jp < 5; ++jp) {
                uint4 p0 = c_blob.pp[jp][0];
                uint4 p1 = c_blob.pp[jp][1];
                uint4 p2 = c_blob.pp[jp][2];
                uint4 p3 = c_blob.pp[jp][3];

                __half2 S[4], D[4];
                #pragma unroll
                for (int k = 0; k < 4; ++k)
                    S[k] = __hfma2(u2h(p0.x), bs[k][0], u2h(p3.y));   // + b1
                #pragma unroll
                for (int k = 0; k < 4; ++k)
                    D[k] = __hmul2(u2h(p1.z), bd[k][0]);
                #pragma unroll
                for (int k = 0; k < 4; ++k) S[k] = __hfma2(u2h(p0.y), bs[k][1], S[k]);
                #pragma unroll
                for (int k = 0; k < 4; ++k) D[k] = __hfma2(u2h(p1.w), bd[k][1], D[k]);
                #pragma unroll
                for (int k = 0; k < 4; ++k) S[k] = __hfma2(u2h(p0.z), bs[k][2], S[k]);
                #pragma unroll
                for (int k = 0; k < 4; ++k) D[k] = __hfma2(u2h(p2.x), bd[k][2], D[k]);
                #pragma unroll
                for (int k = 0; k < 4; ++k) S[k] = __hfma2(u2h(p0.w), bs[k][3], S[k]);
                #pragma unroll
                for (int k = 0; k < 4; ++k) D[k] = __hfma2(u2h(p2.y), bd[k][3], D[k]);
                #pragma unroll
                for (int k = 0; k < 4; ++k) S[k] = __hfma2(u2h(p1.x), bs[k][4], S[k]);
                #pragma unroll
                for (int k = 0; k < 4; ++k) D[k] = __hfma2(u2h(p2.z), bd[k][4], D[k]);
                #pragma unroll
                for (int k = 0; k < 4; ++k) S[k] = __hfma2(u2h(p1.y), bs[k][5], S[k]);
                #pragma unroll
                for (int k = 0; k < 4; ++k) D[k] = __hfma2(u2h(p2.w), bd[k][5], D[k]);

                #pragma unroll
                for (int k = 0; k < 4; ++k) {
                    __half2 U = __hfma2(fe2[k], u2h(p3.x), S[k]);
                    __half2 V = __hfma2(fT2[k], u2h(p3.x), S[k]);
                    __half2 hf = __hmax2(__hadd2(U, D[k]), zero);
                    __half2 hr = __hmax2(__hsub2(V, D[k]), zero);
                    acc[k] = __hfma2(__hadd2(hf, hr), u2h(p3.z), acc[k]);
                }
            }

            float b2d = c_blob.b2d;
            float4 o;
            float* op = &o.x;
            #pragma unroll
            for (int k = 0; k < 4; ++k) {
                float2 a = __half22float2(acc[k]);
                float d = a.x + a.y + b2d;
                op[k] = 1.0f / (1.0f + __expf(-d));
            }
            *reinterpret_cast<float4*>(out + e0) = o;
        }
    } else {
        for (int e = tid; e < E; e += stride) {
            int s = min(max(ei[e], 0), Nm1);
            int t = min(max(ei[(size_t)E + e], 0), Nm1);
            uint4 xs = __ldg(&g_xtab[s]);
            uint4 xt = __ldg(&g_xtab[t]);

            __half2 s0 = __hadd2(u2h(xs.x), u2h(xt.x));
            __half2 s1 = __hadd2(u2h(xs.y), u2h(xt.y));
            __half2 s2 = __hadd2(u2h(xs.z), u2h(xt.z));
            __half2 d0 = __hsub2(u2h(xs.x), u2h(xt.x));
            __half2 d1 = __hsub2(u2h(xs.y), u2h(xt.y));
            __half2 d2 = __hsub2(u2h(xs.z), u2h(xt.z));
            __half2 bs[6] = { __low2half2(s0), __high2half2(s0),
                              __low2half2(s1), __high2half2(s1),
                              __low2half2(s2), __high2half2(s2) };
            __half2 bd[6] = { __low2half2(d0), __high2half2(d0),
                              __low2half2(d1), __high2half2(d1),
                              __low2half2(d2), __high2half2(d2) };
            __half2 fe2 = __float2half2_rn(ea[e]);
            __half2 fT2 = __float2half2_rn(eaT[e]);
            __half2 acc = zero;
            #pragma unroll
            for (int jp = 0; jp < 5; ++jp) {
                uint4 p0 = c_blob.pp[jp][0];
                uint4 p1 = c_blob.pp[jp][1];
                uint4 p2 = c_blob.pp[jp][2];
                uint4 p3 = c_blob.pp[jp][3];
                __half2 S = __hfma2(u2h(p0.x), bs[0], u2h(p3.y));
                S = __hfma2(u2h(p0.y), bs[1], S);
                S = __hfma2(u2h(p0.z), bs[2], S);
                S = __hfma2(u2h(p0.w), bs[3], S);
                S = __hfma2(u2h(p1.x), bs[4], S);
                S = __hfma2(u2h(p1.y), bs[5], S);
                __half2 D = __hmul2(u2h(p1.z), bd[0]);
                D = __hfma2(u2h(p1.w), bd[1], D);
                D = __hfma2(u2h(p2.x), bd[2], D);
                D = __hfma2(u2h(p2.y), bd[3], D);
                D = __hfma2(u2h(p2.z), bd[4], D);
                D = __hfma2(u2h(p2.w), bd[5], D);
                __half2 U = __hfma2(fe2, u2h(p3.x), S);
                __half2 V = __hfma2(fT2, u2h(p3.x), S);
                __half2 hf = __hmax2(__hadd2(U, D), zero);
                __half2 hr = __hmax2(__hsub2(V, D), zero);
                acc = __hfma2(__hadd2(hf, hr), u2h(p3.z), acc);
            }
            float2 a = __half22float2(acc);
            float d = a.x + a.y + c_blob.b2d;
            out[e] = 1.0f / (1.0f + __expf(-d));
        }
    }
}

extern "C" void kernel_launch(void* const* d_in, const int* in_sizes, int n_in,
                              void* d_out, int out_size)
{
    const float* x   = (const float*)d_in[0];
    const int*   ei  = (const int*)d_in[1];
    const float* ea  = (const float*)d_in[2];
    const float* eaT = (const float*)d_in[3];
    const float* W1  = (const float*)d_in[4];
    const float* b1  = (const float*)d_in[5];
    const float* W2  = (const float*)d_in[6];
    const float* b2  = (const float*)d_in[7];
    float*       out = (float*)d_out;

    int N = in_sizes[0] / 6;
    if (N > N_NODES) N = N_NODES;
    int E = in_sizes[2];

    precompute_kernel<<<(N + 255) / 256, 256>>>(x, W1, b1, W2, b2, N);

    void* src = nullptr;
    cudaGetSymbolAddress(&src, g_blob);
    cudaMemcpyToSymbolAsync(c_blob, src, sizeof(ParamBlob), 0,
                            cudaMemcpyDeviceToDevice, 0);

    int work_items = (E + 3) / 4;
    int blocks = 148 * 3;                       // one wave at 3 blocks/SM
    int max_blocks = (work_items + 255) / 256;
    if (blocks > max_blocks) blocks = max_blocks;
    if (blocks < 1) blocks = 1;
    edge_kernel<<<blocks, 256>>>(ei, ea, eaT, out, E, N);
}

// round 16
// speedup vs baseline: 4.5808x; 1.0278x over previous
#include <cuda_runtime.h>
#include <cuda_fp16.h>

// EdgeMLP, gather-minimized, grid-stride depth-8, jp-outer interleaved,
// 4 CTAs/SM occupancy push:
//   node table: x in fp16, 16B record -> ONE LDG.128 per endpoint gather.
//   sum = xs+xt, dif = xs-xt; S = sum@Ws + b1, D = dif@Wd
//   h_f = relu(S + fe*w1e + D),  h_r = relu(S + feT*w1e - D)
//   out = sigmoid((h_f+h_r) . (0.5*w2diff) + b2diff)
// The 4 edges of a quad advance TOGETHER through each j-pair (8 independent
// FMA chains in flight). 32 warps/SM keep L1tex fed during compute phases.

#define N_NODES 100000
#define HID 10

struct ParamBlob {
    uint4 pp[5][4];     // per j-pair: Ws[6], Wd[6], w1e, b1, w2d, pad
    float b2d;
    float pad[3];
};

__device__   ParamBlob g_blob;
__constant__ ParamBlob c_blob;

__device__ uint4 g_xtab[N_NODES];

__device__ __forceinline__ __half2 u2h(unsigned int u)
{
    return *reinterpret_cast<__half2*>(&u);
}
__device__ __forceinline__ unsigned int h2u(__half2 h)
{
    return *reinterpret_cast<unsigned int*>(&h);
}

__global__ __launch_bounds__(512)
void precompute_kernel(const float* __restrict__ x,
                       const float* __restrict__ W1,
                       const float* __restrict__ b1,
                       const float* __restrict__ W2,
                       const float* __restrict__ b2,
                       int N)
{
    int n = blockIdx.x * blockDim.x + threadIdx.x;

    // parallel param prep: threads 0..4 one j-pair each, thread 5 b2d
    if (blockIdx.x == 0 && threadIdx.x < 5) {
        int jp = threadIdx.x;
        int j0 = 2 * jp, j1 = 2 * jp + 1;
        unsigned int slot[16];
        #pragma unroll
        for (int i = 0; i < 6; ++i) {
            float a0 = W1[i * HID + j0],       a1 = W1[i * HID + j1];
            float c0 = W1[(6 + i) * HID + j0], c1 = W1[(6 + i) * HID + j1];
            slot[i]     = h2u(__floats2half2_rn(0.5f * (a0 + c0), 0.5f * (a1 + c1)));
            slot[6 + i] = h2u(__floats2half2_rn(0.5f * (a0 - c0), 0.5f * (a1 - c1)));
        }
        slot[12] = h2u(__floats2half2_rn(W1[12 * HID + j0], W1[12 * HID + j1]));
        slot[13] = h2u(__floats2half2_rn(b1[j0], b1[j1]));
        slot[14] = h2u(__floats2half2_rn(0.5f * (W2[j0 * 2 + 1] - W2[j0 * 2]),
                                         0.5f * (W2[j1 * 2 + 1] - W2[j1 * 2])));
        slot[15] = 0u;
        g_blob.pp[jp][0] = make_uint4(slot[0],  slot[1],  slot[2],  slot[3]);
        g_blob.pp[jp][1] = make_uint4(slot[4],  slot[5],  slot[6],  slot[7]);
        g_blob.pp[jp][2] = make_uint4(slot[8],  slot[9],  slot[10], slot[11]);
        g_blob.pp[jp][3] = make_uint4(slot[12], slot[13], slot[14], slot[15]);
    }
    if (blockIdx.x == 0 && threadIdx.x == 5) {
        g_blob.b2d = b2[1] - b2[0];
    }

    if (n >= N) return;

    float x0 = x[n * 6 + 0], x1 = x[n * 6 + 1], x2 = x[n * 6 + 2];
    float x3 = x[n * 6 + 3], x4 = x[n * 6 + 4], x5 = x[n * 6 + 5];
    g_xtab[n] = make_uint4(h2u(__floats2half2_rn(x0, x1)),
                           h2u(__floats2half2_rn(x2, x3)),
                           h2u(__floats2half2_rn(x4, x5)),
                           0u);
}

__global__ __launch_bounds__(256, 4)
void edge_kernel(const int* __restrict__ ei,        // [2, E] int32
                 const float* __restrict__ ea,
                 const float* __restrict__ eaT,
                 float* __restrict__ out,
                 int E, int N)
{
    int Nm1 = N - 1;
    int stride = gridDim.x * blockDim.x;
    int tid = blockIdx.x * blockDim.x + threadIdx.x;

    const __half2 zero = __float2half2_rn(0.0f);

    if ((E & 3) == 0) {
        int nq = E >> 2;
        for (int q = tid; q < nq; q += stride) {
            int e0 = q << 2;
            int4   ss = *reinterpret_cast<const int4*>(ei + e0);
            int4   tt = *reinterpret_cast<const int4*>(ei + (size_t)E + e0);
            float4 fe = *reinterpret_cast<const float4*>(ea + e0);
            float4 fT = *reinterpret_cast<const float4*>(eaT + e0);

            int sv[4] = { min(max(ss.x, 0), Nm1), min(max(ss.y, 0), Nm1),
                          min(max(ss.z, 0), Nm1), min(max(ss.w, 0), Nm1) };
            int tv[4] = { min(max(tt.x, 0), Nm1), min(max(tt.y, 0), Nm1),
                          min(max(tt.z, 0), Nm1), min(max(tt.w, 0), Nm1) };

            // 8 front-batched gathers
            uint4 X[4], T[4];
            #pragma unroll
            for (int k = 0; k < 4; ++k) {
                X[k] = __ldg(&g_xtab[sv[k]]);
                T[k] = __ldg(&g_xtab[tv[k]]);
            }

            // broadcast-pair features for all 4 edges
            __half2 bs[4][6], bd[4][6], fe2[4], fT2[4];
            float fev[4] = { fe.x, fe.y, fe.z, fe.w };
            float fTv[4] = { fT.x, fT.y, fT.z, fT.w };
            #pragma unroll
            for (int k = 0; k < 4; ++k) {
                __half2 s0 = __hadd2(u2h(X[k].x), u2h(T[k].x));
                __half2 s1 = __hadd2(u2h(X[k].y), u2h(T[k].y));
                __half2 s2 = __hadd2(u2h(X[k].z), u2h(T[k].z));
                __half2 d0 = __hsub2(u2h(X[k].x), u2h(T[k].x));
                __half2 d1 = __hsub2(u2h(X[k].y), u2h(T[k].y));
                __half2 d2 = __hsub2(u2h(X[k].z), u2h(T[k].z));
                bs[k][0] = __low2half2(s0);  bs[k][1] = __high2half2(s0);
                bs[k][2] = __low2half2(s1);  bs[k][3] = __high2half2(s1);
                bs[k][4] = __low2half2(s2);  bs[k][5] = __high2half2(s2);
                bd[k][0] = __low2half2(d0);  bd[k][1] = __high2half2(d0);
                bd[k][2] = __low2half2(d1);  bd[k][3] = __high2half2(d1);
                bd[k][4] = __low2half2(d2);  bd[k][5] = __high2half2(d2);
                fe2[k] = __float2half2_rn(fev[k]);
                fT2[k] = __float2half2_rn(fTv[k]);
            }

            __half2 acc[4] = { zero, zero, zero, zero };

            // jp-outer: 4 edges advance together -> 8 independent FMA chains
            #pragma unroll
            for (int jp = 0; jp < 5; ++jp) {
                uint4 p0 = c_blob.pp[jp][0];
                uint4 p1 = c_blob.pp[jp][1];
                uint4 p2 = c_blob.pp[jp][2];
                uint4 p3 = c_blob.pp[jp][3];

                __half2 S[4], D[4];
                #pragma unroll
                for (int k = 0; k < 4; ++k)
                    S[k] = __hfma2(u2h(p0.x), bs[k][0], u2h(p3.y));   // + b1
                #pragma unroll
                for (int k = 0; k < 4; ++k)
                    D[k] = __hmul2(u2h(p1.z), bd[k][0]);
                #pragma unroll
                for (int k = 0; k < 4; ++k) S[k] = __hfma2(u2h(p0.y), bs[k][1], S[k]);
                #pragma unroll
                for (int k = 0; k < 4; ++k) D[k] = __hfma2(u2h(p1.w), bd[k][1], D[k]);
                #pragma unroll
                for (int k = 0; k < 4; ++k) S[k] = __hfma2(u2h(p0.z), bs[k][2], S[k]);
                #pragma unroll
                for (int k = 0; k < 4; ++k) D[k] = __hfma2(u2h(p2.x), bd[k][2], D[k]);
                #pragma unroll
                for (int k = 0; k < 4; ++k) S[k] = __hfma2(u2h(p0.w), bs[k][3], S[k]);
                #pragma unroll
                for (int k = 0; k < 4; ++k) D[k] = __hfma2(u2h(p2.y), bd[k][3], D[k]);
                #pragma unroll
                for (int k = 0; k < 4; ++k) S[k] = __hfma2(u2h(p1.x), bs[k][4], S[k]);
                #pragma unroll
                for (int k = 0; k < 4; ++k) D[k] = __hfma2(u2h(p2.z), bd[k][4], D[k]);
                #pragma unroll
                for (int k = 0; k < 4; ++k) S[k] = __hfma2(u2h(p1.y), bs[k][5], S[k]);
                #pragma unroll
                for (int k = 0; k < 4; ++k) D[k] = __hfma2(u2h(p2.w), bd[k][5], D[k]);

                #pragma unroll
                for (int k = 0; k < 4; ++k) {
                    __half2 U = __hfma2(fe2[k], u2h(p3.x), S[k]);
                    __half2 V = __hfma2(fT2[k], u2h(p3.x), S[k]);
                    __half2 hf = __hmax2(__hadd2(U, D[k]), zero);
                    __half2 hr = __hmax2(__hsub2(V, D[k]), zero);
                    acc[k] = __hfma2(__hadd2(hf, hr), u2h(p3.z), acc[k]);
                }
            }

            float b2d = c_blob.b2d;
            float4 o;
            float* op = &o.x;
            #pragma unroll
            for (int k = 0; k < 4; ++k) {
                float2 a = __half22float2(acc[k]);
                float d = a.x + a.y + b2d;
                op[k] = 1.0f / (1.0f + __expf(-d));
            }
            *reinterpret_cast<float4*>(out + e0) = o;
        }
    } else {
        for (int e = tid; e < E; e += stride) {
            int s = min(max(ei[e], 0), Nm1);
            int t = min(max(ei[(size_t)E + e], 0), Nm1);
            uint4 xs = __ldg(&g_xtab[s]);
            uint4 xt = __ldg(&g_xtab[t]);

            __half2 s0 = __hadd2(u2h(xs.x), u2h(xt.x));
            __half2 s1 = __hadd2(u2h(xs.y), u2h(xt.y));
            __half2 s2 = __hadd2(u2h(xs.z), u2h(xt.z));
            __half2 d0 = __hsub2(u2h(xs.x), u2h(xt.x));
            __half2 d1 = __hsub2(u2h(xs.y), u2h(xt.y));
            __half2 d2 = __hsub2(u2h(xs.z), u2h(xt.z));
            __half2 bs[6] = { __low2half2(s0), __high2half2(s0),
                              __low2half2(s1), __high2half2(s1),
                              __low2half2(s2), __high2half2(s2) };
            __half2 bd[6] = { __low2half2(d0), __high2half2(d0),
                              __low2half2(d1), __high2half2(d1),
                              __low2half2(d2), __high2half2(d2) };
            __half2 fe2 = __float2half2_rn(ea[e]);
            __half2 fT2 = __float2half2_rn(eaT[e]);
            __half2 acc = zero;
            #pragma unroll
            for (int jp = 0; jp < 5; ++jp) {
                uint4 p0 = c_blob.pp[jp][0];
                uint4 p1 = c_blob.pp[jp][1];
                uint4 p2 = c_blob.pp[jp][2];
                uint4 p3 = c_blob.pp[jp][3];
                __half2 S = __hfma2(u2h(p0.x), bs[0], u2h(p3.y));
                S = __hfma2(u2h(p0.y), bs[1], S);
                S = __hfma2(u2h(p0.z), bs[2], S);
                S = __hfma2(u2h(p0.w), bs[3], S);
                S = __hfma2(u2h(p1.x), bs[4], S);
                S = __hfma2(u2h(p1.y), bs[5], S);
                __half2 D = __hmul2(u2h(p1.z), bd[0]);
                D = __hfma2(u2h(p1.w), bd[1], D);
                D = __hfma2(u2h(p2.x), bd[2], D);
                D = __hfma2(u2h(p2.y), bd[3], D);
                D = __hfma2(u2h(p2.z), bd[4], D);
                D = __hfma2(u2h(p2.w), bd[5], D);
                __half2 U = __hfma2(fe2, u2h(p3.x), S);
                __half2 V = __hfma2(fT2, u2h(p3.x), S);
                __half2 hf = __hmax2(__hadd2(U, D), zero);
                __half2 hr = __hmax2(__hsub2(V, D), zero);
                acc = __hfma2(__hadd2(hf, hr), u2h(p3.z), acc);
            }
            float2 a = __half22float2(acc);
            float d = a.x + a.y + c_blob.b2d;
            out[e] = 1.0f / (1.0f + __expf(-d));
        }
    }
}

extern "C" void kernel_launch(void* const* d_in, const int* in_sizes, int n_in,
                              void* d_out, int out_size)
{
    const float* x   = (const float*)d_in[0];
    const int*   ei  = (const int*)d_in[1];
    const float* ea  = (const float*)d_in[2];
    const float* eaT = (const float*)d_in[3];
    const float* W1  = (const float*)d_in[4];
    const float* b1  = (const float*)d_in[5];
    const float* W2  = (const float*)d_in[6];
    const float* b2  = (const float*)d_in[7];
    float*       out = (float*)d_out;

    int N = in_sizes[0] / 6;
    if (N > N_NODES) N = N_NODES;
    int E = in_sizes[2];

    precompute_kernel<<<(N + 511) / 512, 512>>>(x, W1, b1, W2, b2, N);

    void* src = nullptr;
    cudaGetSymbolAddress(&src, g_blob);
    cudaMemcpyToSymbolAsync(c_blob, src, sizeof(ParamBlob), 0,
                            cudaMemcpyDeviceToDevice, 0);

    int work_items = (E + 3) / 4;
    int blocks = 148 * 4;                       // one wave at 4 blocks/SM
    int max_blocks = (work_items + 255) / 256;
    if (blocks > max_blocks) blocks = max_blocks;
    if (blocks < 1) blocks = 1;
    edge_kernel<<<blocks, 256>>>(ei, ea, eaT, out, E, N);
}